// round 3
// baseline (speedup 1.0000x reference)
#include <cuda_runtime.h>

#define NN 100000
#define NE 1600000
#define NG 1000
#define F1 64
#define F2 128

// Scratch (device globals — no allocation allowed)
__device__ float d_deg[NN];
__device__ float d_dinv[NN];
__device__ __align__(16) float d_g1[NN * F1];
__device__ __align__(16) float d_acc1[NN * F1];
__device__ __align__(16) float d_g2[NN * F2];
__device__ __align__(16) float d_acc2[NN * F2];
__device__ __align__(16) float d_pool[NG * F2];
__device__ float d_cnt[NG];

__device__ __forceinline__ float relu(float v) { return v > 0.f ? v : 0.f; }

// ---------------------------------------------------------------------------
// 0) Zero accumulators, deg=1 (self loop), pool=0, cnt=0
// ---------------------------------------------------------------------------
__global__ void k_init() {
    int i = blockIdx.x * blockDim.x + threadIdx.x;
    if (i < NN * F2) d_acc2[i] = 0.f;
    if (i < NN * F1) d_acc1[i] = 0.f;
    if (i < NN)      d_deg[i]  = 1.f;
    if (i < NG * F2) d_pool[i] = 0.f;
    if (i < NG)      d_cnt[i]  = 0.f;
}

// ---------------------------------------------------------------------------
// 1) In-degree (dst side, matching reference), then dinv = rsqrt(deg)
//    NOTE: edge_index is int32 (JAX x64 disabled downgrades int64->int32).
// ---------------------------------------------------------------------------
__global__ void k_deg(const int* __restrict__ ei) {
    int i = blockIdx.x * blockDim.x + threadIdx.x;
    if (i >= NE) return;
    int d = ei[NE + i];
    atomicAdd(&d_deg[d], 1.f);
}

__global__ void k_dinv() {
    int i = blockIdx.x * blockDim.x + threadIdx.x;
    if (i < NN) d_dinv[i] = rsqrtf(d_deg[i]);
}

// ---------------------------------------------------------------------------
// 2) g1[v] = dinv[v] * (x[v] @ W1)     [N, 64]
//    16 threads per node, each computes a float4 of outputs.
// ---------------------------------------------------------------------------
__global__ void k_g1(const float* __restrict__ x, const float* __restrict__ W1) {
    __shared__ float w[6 * F1];
    for (int j = threadIdx.x; j < 6 * F1; j += blockDim.x) w[j] = W1[j];
    __syncthreads();
    int i = blockIdx.x * blockDim.x + threadIdx.x;
    if (i >= NN * 16) return;
    int n = i >> 4;
    int c = (i & 15) * 4;
    float xv[6];
#pragma unroll
    for (int k = 0; k < 6; k++) xv[k] = x[n * 6 + k];
    float dv = d_dinv[n];
    float4 o;
    float* po = (float*)&o;
#pragma unroll
    for (int j = 0; j < 4; j++) {
        float a = 0.f;
#pragma unroll
        for (int k = 0; k < 6; k++) a += xv[k] * w[k * F1 + c + j];
        po[j] = dv * a;
    }
    *reinterpret_cast<float4*>(&d_g1[n * F1 + c]) = o;
}

// ---------------------------------------------------------------------------
// 3) Edge scatter layer 1: acc1[dst] += g1[src]   (16 lanes/edge, 4 feats ea)
// ---------------------------------------------------------------------------
__global__ void k_sc1(const int* __restrict__ ei) {
    int i = blockIdx.x * blockDim.x + threadIdx.x;
    if (i >= NE * 16) return;
    int e = i >> 4;
    int c = (i & 15) * 4;
    int s = ei[e];
    int d = ei[NE + e];
    float4 v = *reinterpret_cast<const float4*>(&d_g1[s * F1 + c]);
    float* p = &d_acc1[d * F1 + c];
    atomicAdd(p + 0, v.x);
    atomicAdd(p + 1, v.y);
    atomicAdd(p + 2, v.z);
    atomicAdd(p + 3, v.w);
}

// ---------------------------------------------------------------------------
// 4) out1[v] = relu(dinv*(acc1+g1) + b1);  g2[v] = dinv[v]*(out1 @ W2)
//    128 threads/block (one output feature each), 16 nodes per block,
//    W2 (64x128 = 32KB) staged in smem.
// ---------------------------------------------------------------------------
__global__ void k_l2(const float* __restrict__ b1, const float* __restrict__ W2) {
    __shared__ float w[F1 * F2];
    __shared__ float in_s[F1];
    int tid = threadIdx.x;
    for (int j = tid; j < F1 * F2; j += 128) w[j] = W2[j];
    int base = blockIdx.x * 16;
    for (int t = 0; t < 16; t++) {
        int n = base + t;
        float dv = d_dinv[n];
        __syncthreads();
        if (tid < F1) {
            float v = dv * (d_acc1[n * F1 + tid] + d_g1[n * F1 + tid]) + b1[tid];
            in_s[tid] = relu(v);
        }
        __syncthreads();
        float a = 0.f;
#pragma unroll
        for (int k = 0; k < F1; k++) a += in_s[k] * w[k * F2 + tid];
        d_g2[n * F2 + tid] = dv * a;
    }
}

// ---------------------------------------------------------------------------
// 5) Edge scatter layer 2: acc2[dst] += g2[src]   (32 lanes/edge, 4 feats ea)
// ---------------------------------------------------------------------------
__global__ void k_sc2(const int* __restrict__ ei) {
    int i = blockIdx.x * blockDim.x + threadIdx.x;
    if (i >= NE * 32) return;
    int e = i >> 5;
    int c = (i & 31) * 4;
    int s = ei[e];
    int d = ei[NE + e];
    float4 v = *reinterpret_cast<const float4*>(&d_g2[s * F2 + c]);
    float* p = &d_acc2[d * F2 + c];
    atomicAdd(p + 0, v.x);
    atomicAdd(p + 1, v.y);
    atomicAdd(p + 2, v.z);
    atomicAdd(p + 3, v.w);
}

// ---------------------------------------------------------------------------
// 6) out2[v] = relu(dinv*(acc2+g2) + b2); pool[batch[v]] += out2; cnt++
// ---------------------------------------------------------------------------
__global__ void k_pool(const float* __restrict__ b2, const int* __restrict__ batch) {
    int i = blockIdx.x * blockDim.x + threadIdx.x;
    if (i >= NN * 32) return;
    int n = i >> 5;
    int c = (i & 31) * 4;
    float dv = d_dinv[n];
    float4 a = *reinterpret_cast<const float4*>(&d_acc2[n * F2 + c]);
    float4 g = *reinterpret_cast<const float4*>(&d_g2[n * F2 + c]);
    float4 v;
    v.x = relu(dv * (a.x + g.x) + b2[c + 0]);
    v.y = relu(dv * (a.y + g.y) + b2[c + 1]);
    v.z = relu(dv * (a.z + g.z) + b2[c + 2]);
    v.w = relu(dv * (a.w + g.w) + b2[c + 3]);
    int gid = batch[n];
    float* p = &d_pool[gid * F2 + c];
    atomicAdd(p + 0, v.x);
    atomicAdd(p + 1, v.y);
    atomicAdd(p + 2, v.z);
    atomicAdd(p + 3, v.w);
    if ((i & 31) == 0) atomicAdd(&d_cnt[gid], 1.f);
}

// ---------------------------------------------------------------------------
// 7) out[g] = (pool[g]/max(cnt,1)) @ Wfc + bfc      [1000, 2]
// ---------------------------------------------------------------------------
__global__ void k_fc(const float* __restrict__ Wfc, const float* __restrict__ bfc,
                     float* __restrict__ out) {
    int i = blockIdx.x * blockDim.x + threadIdx.x;
    if (i >= NG * 2) return;
    int g = i >> 1;
    int o = i & 1;
    float cnt = d_cnt[g];
    float inv = 1.f / (cnt > 1.f ? cnt : 1.f);
    float a = 0.f;
#pragma unroll 8
    for (int k = 0; k < F2; k++) a += d_pool[g * F2 + k] * Wfc[k * 2 + o];
    out[i] = a * inv + bfc[o];
}

// ---------------------------------------------------------------------------
extern "C" void kernel_launch(void* const* d_in, const int* in_sizes, int n_in,
                              void* d_out, int out_size) {
    const float* x   = (const float*)d_in[0];
    const int*   ei  = (const int*)d_in[1];   // int32! (JAX x64 disabled)
    const int*   bat = (const int*)d_in[2];   // int32!
    const float* W1  = (const float*)d_in[3];
    const float* b1  = (const float*)d_in[4];
    const float* W2  = (const float*)d_in[5];
    const float* b2  = (const float*)d_in[6];
    const float* Wfc = (const float*)d_in[7];
    const float* bfc = (const float*)d_in[8];
    float*       out = (float*)d_out;

    k_init<<<(NN * F2 + 255) / 256, 256>>>();
    k_deg<<<(NE + 255) / 256, 256>>>(ei);
    k_dinv<<<(NN + 255) / 256, 256>>>();
    k_g1<<<(NN * 16 + 255) / 256, 256>>>(x, W1);
    k_sc1<<<(NE * 16 + 255) / 256, 256>>>(ei);
    k_l2<<<NN / 16, 128>>>(b1, W2);
    k_sc2<<<(NE * 32 + 255) / 256, 256>>>(ei);
    k_pool<<<(NN * 32 + 255) / 256, 256>>>(b2, bat);
    k_fc<<<(NG * 2 + 255) / 256, 256>>>(Wfc, bfc, out);
}

// round 4
// speedup vs baseline: 1.7248x; 1.7248x over previous
#include <cuda_runtime.h>

#define NN 100000
#define NE 1600000
#define NG 1000
#define F1 64
#define F2 128

// Scratch (device globals — no allocation allowed)
__device__ float d_deg[NN];
__device__ float d_dinv[NN];
__device__ __align__(16) float d_g1[NN * F1];
__device__ __align__(16) float d_acc1[NN * F1];
__device__ __align__(16) float d_g2[NN * F2];
__device__ __align__(16) float d_acc2[NN * F2];
__device__ __align__(16) float d_pool[NG * F2];
__device__ float d_cnt[NG];

__device__ __forceinline__ float relu(float v) { return v > 0.f ? v : 0.f; }

// ---------------------------------------------------------------------------
// 0) Zero accumulators, deg=1 (self loop), pool=0, cnt=0
// ---------------------------------------------------------------------------
__global__ void k_init() {
    int i = blockIdx.x * blockDim.x + threadIdx.x;
    if (i < NN * F2) d_acc2[i] = 0.f;
    if (i < NN * F1) d_acc1[i] = 0.f;
    if (i < NN)      d_deg[i]  = 1.f;
    if (i < NG * F2) d_pool[i] = 0.f;
    if (i < NG)      d_cnt[i]  = 0.f;
}

// ---------------------------------------------------------------------------
// 1) In-degree (dst side, matching reference), then dinv = rsqrt(deg)
//    edge_index is int32 (JAX x64 disabled downgrades int64->int32).
// ---------------------------------------------------------------------------
__global__ void k_deg(const int* __restrict__ ei) {
    int i = blockIdx.x * blockDim.x + threadIdx.x;
    if (i >= NE) return;
    int d = ei[NE + i];
    atomicAdd(&d_deg[d], 1.f);
}

__global__ void k_dinv() {
    int i = blockIdx.x * blockDim.x + threadIdx.x;
    if (i < NN) d_dinv[i] = rsqrtf(d_deg[i]);
}

// ---------------------------------------------------------------------------
// 2) g1[v] = dinv[v] * (x[v] @ W1)     [N, 64]
//    16 threads per node, each computes a float4 of outputs.
// ---------------------------------------------------------------------------
__global__ void k_g1(const float* __restrict__ x, const float* __restrict__ W1) {
    __shared__ float w[6 * F1];
    for (int j = threadIdx.x; j < 6 * F1; j += blockDim.x) w[j] = W1[j];
    __syncthreads();
    int i = blockIdx.x * blockDim.x + threadIdx.x;
    if (i >= NN * 16) return;
    int n = i >> 4;
    int c = (i & 15) * 4;
    float xv[6];
#pragma unroll
    for (int k = 0; k < 6; k++) xv[k] = x[n * 6 + k];
    float dv = d_dinv[n];
    float4 o;
    float* po = (float*)&o;
#pragma unroll
    for (int j = 0; j < 4; j++) {
        float a = 0.f;
#pragma unroll
        for (int k = 0; k < 6; k++) a += xv[k] * w[k * F1 + c + j];
        po[j] = dv * a;
    }
    *reinterpret_cast<float4*>(&d_g1[n * F1 + c]) = o;
}

// ---------------------------------------------------------------------------
// 3) Edge scatter layer 1: acc1[dst] += g1[src]
//    16 lanes/edge, one float4 vector reduction per lane (sm_90+ native).
// ---------------------------------------------------------------------------
__global__ void k_sc1(const int* __restrict__ ei) {
    int i = blockIdx.x * blockDim.x + threadIdx.x;
    if (i >= NE * 16) return;
    int e = i >> 4;
    int c = (i & 15) * 4;
    int s = ei[e];
    int d = ei[NE + e];
    float4 v = *reinterpret_cast<const float4*>(&d_g1[s * F1 + c]);
    atomicAdd(reinterpret_cast<float4*>(&d_acc1[d * F1 + c]), v);
}

// ---------------------------------------------------------------------------
// 4) out1[v] = relu(dinv*(acc1+g1) + b1);  g2[v] = dinv[v]*(out1 @ W2)
//    128 threads/block (one output feature each), 16 nodes per block,
//    W2 (64x128 = 32KB) staged in smem.
// ---------------------------------------------------------------------------
__global__ void k_l2(const float* __restrict__ b1, const float* __restrict__ W2) {
    __shared__ float w[F1 * F2];
    __shared__ float in_s[F1];
    int tid = threadIdx.x;
    for (int j = tid; j < F1 * F2; j += 128) w[j] = W2[j];
    int base = blockIdx.x * 16;
    for (int t = 0; t < 16; t++) {
        int n = base + t;
        float dv = d_dinv[n];
        __syncthreads();
        if (tid < F1) {
            float v = dv * (d_acc1[n * F1 + tid] + d_g1[n * F1 + tid]) + b1[tid];
            in_s[tid] = relu(v);
        }
        __syncthreads();
        float a = 0.f;
#pragma unroll
        for (int k = 0; k < F1; k++) a += in_s[k] * w[k * F2 + tid];
        d_g2[n * F2 + tid] = dv * a;
    }
}

// ---------------------------------------------------------------------------
// 5) Edge scatter layer 2: acc2[dst] += g2[src]
//    32 lanes/edge, one float4 vector reduction per lane.
// ---------------------------------------------------------------------------
__global__ void k_sc2(const int* __restrict__ ei) {
    int i = blockIdx.x * blockDim.x + threadIdx.x;
    if (i >= NE * 32) return;
    int e = i >> 5;
    int c = (i & 31) * 4;
    int s = ei[e];
    int d = ei[NE + e];
    float4 v = *reinterpret_cast<const float4*>(&d_g2[s * F2 + c]);
    atomicAdd(reinterpret_cast<float4*>(&d_acc2[d * F2 + c]), v);
}

// ---------------------------------------------------------------------------
// 6) out2[v] = relu(dinv*(acc2+g2) + b2); pool[batch[v]] += out2; cnt++
// ---------------------------------------------------------------------------
__global__ void k_pool(const float* __restrict__ b2, const int* __restrict__ batch) {
    int i = blockIdx.x * blockDim.x + threadIdx.x;
    if (i >= NN * 32) return;
    int n = i >> 5;
    int c = (i & 31) * 4;
    float dv = d_dinv[n];
    float4 a = *reinterpret_cast<const float4*>(&d_acc2[n * F2 + c]);
    float4 g = *reinterpret_cast<const float4*>(&d_g2[n * F2 + c]);
    float4 v;
    v.x = relu(dv * (a.x + g.x) + b2[c + 0]);
    v.y = relu(dv * (a.y + g.y) + b2[c + 1]);
    v.z = relu(dv * (a.z + g.z) + b2[c + 2]);
    v.w = relu(dv * (a.w + g.w) + b2[c + 3]);
    int gid = batch[n];
    atomicAdd(reinterpret_cast<float4*>(&d_pool[gid * F2 + c]), v);
    if ((i & 31) == 0) atomicAdd(&d_cnt[gid], 1.f);
}

// ---------------------------------------------------------------------------
// 7) out[g] = (pool[g]/max(cnt,1)) @ Wfc + bfc      [1000, 2]
// ---------------------------------------------------------------------------
__global__ void k_fc(const float* __restrict__ Wfc, const float* __restrict__ bfc,
                     float* __restrict__ out) {
    int i = blockIdx.x * blockDim.x + threadIdx.x;
    if (i >= NG * 2) return;
    int g = i >> 1;
    int o = i & 1;
    float cnt = d_cnt[g];
    float inv = 1.f / (cnt > 1.f ? cnt : 1.f);
    float a = 0.f;
#pragma unroll 8
    for (int k = 0; k < F2; k++) a += d_pool[g * F2 + k] * Wfc[k * 2 + o];
    out[i] = a * inv + bfc[o];
}

// ---------------------------------------------------------------------------
extern "C" void kernel_launch(void* const* d_in, const int* in_sizes, int n_in,
                              void* d_out, int out_size) {
    const float* x   = (const float*)d_in[0];
    const int*   ei  = (const int*)d_in[1];   // int32 (JAX x64 disabled)
    const int*   bat = (const int*)d_in[2];   // int32
    const float* W1  = (const float*)d_in[3];
    const float* b1  = (const float*)d_in[4];
    const float* W2  = (const float*)d_in[5];
    const float* b2  = (const float*)d_in[6];
    const float* Wfc = (const float*)d_in[7];
    const float* bfc = (const float*)d_in[8];
    float*       out = (float*)d_out;

    k_init<<<(NN * F2 + 255) / 256, 256>>>();
    k_deg<<<(NE + 255) / 256, 256>>>(ei);
    k_dinv<<<(NN + 255) / 256, 256>>>();
    k_g1<<<(NN * 16 + 255) / 256, 256>>>(x, W1);
    k_sc1<<<(NE * 16 + 255) / 256, 256>>>(ei);
    k_l2<<<NN / 16, 128>>>(b1, W2);
    k_sc2<<<(NE * 32 + 255) / 256, 256>>>(ei);
    k_pool<<<(NN * 32 + 255) / 256, 256>>>(b2, bat);
    k_fc<<<(NG * 2 + 255) / 256, 256>>>(Wfc, bfc, out);
}

// round 5
// speedup vs baseline: 3.0000x; 1.7394x over previous
#include <cuda_runtime.h>

#define NN 100000
#define NE 1600000
#define NG 1000
#define F1 64
#define F2 128
#define P0 8   // padded width of layer-0 scatter features (6 used)

// Scratch (device globals — no allocation allowed)
__device__ float d_deg[NN];
__device__ float d_dinv[NN];
__device__ __align__(16) float d_p0[NN * P0];    // dinv * x   (padded 6->8)
__device__ __align__(16) float d_acc0[NN * P0];  // edge sum of p0
__device__ __align__(16) float d_p1[NN * F1];    // dinv * relu(out1)
__device__ __align__(16) float d_acc1[NN * F1];  // edge sum of p1
__device__ __align__(16) float d_pool[NG * F2];
__device__ float d_cnt[NG];

__device__ __forceinline__ float relu(float v) { return v > 0.f ? v : 0.f; }

// ---------------------------------------------------------------------------
// 0) Zero accumulators, deg=1 (self loop), pool=0, cnt=0
// ---------------------------------------------------------------------------
__global__ void k_init() {
    int i = blockIdx.x * blockDim.x + threadIdx.x;
    if (i < NN * F1) d_acc1[i] = 0.f;
    if (i < NN * P0) d_acc0[i] = 0.f;
    if (i < NN)      d_deg[i]  = 1.f;
    if (i < NG * F2) d_pool[i] = 0.f;
    if (i < NG)      d_cnt[i]  = 0.f;
}

// ---------------------------------------------------------------------------
// 1) In-degree (dst side, matching reference), then dinv = rsqrt(deg)
// ---------------------------------------------------------------------------
__global__ void k_deg(const int* __restrict__ ei) {
    int i = blockIdx.x * blockDim.x + threadIdx.x;
    if (i >= NE) return;
    atomicAdd(&d_deg[ei[NE + i]], 1.f);
}

__global__ void k_dinv() {
    int i = blockIdx.x * blockDim.x + threadIdx.x;
    if (i < NN) d_dinv[i] = rsqrtf(d_deg[i]);
}

// ---------------------------------------------------------------------------
// 2) p0[v] = dinv[v] * x[v]   (6 floats, padded to 8)
// ---------------------------------------------------------------------------
__global__ void k_p0(const float* __restrict__ x) {
    int n = blockIdx.x * blockDim.x + threadIdx.x;
    if (n >= NN) return;
    float dv = d_dinv[n];
    float4 a, b;
    a.x = dv * x[n * 6 + 0];
    a.y = dv * x[n * 6 + 1];
    a.z = dv * x[n * 6 + 2];
    a.w = dv * x[n * 6 + 3];
    b.x = dv * x[n * 6 + 4];
    b.y = dv * x[n * 6 + 5];
    b.z = 0.f;
    b.w = 0.f;
    *reinterpret_cast<float4*>(&d_p0[n * P0 + 0]) = a;
    *reinterpret_cast<float4*>(&d_p0[n * P0 + 4]) = b;
}

// ---------------------------------------------------------------------------
// 3) Edge scatter (pre-W1): acc0[dst] += p0[src]   (2 float4 reds / edge)
// ---------------------------------------------------------------------------
__global__ void k_sc0(const int* __restrict__ ei) {
    int i = blockIdx.x * blockDim.x + threadIdx.x;
    if (i >= NE * 2) return;
    int e = i >> 1;
    int c = (i & 1) * 4;
    int s = ei[e];
    int d = ei[NE + e];
    float4 v = *reinterpret_cast<const float4*>(&d_p0[s * P0 + c]);
    atomicAdd(reinterpret_cast<float4*>(&d_acc0[d * P0 + c]), v);
}

// ---------------------------------------------------------------------------
// 4) t = acc0 + p0 (self loop);  out1 = relu(dinv*(t@W1) + b1);
//    p1 = dinv * out1.   16 threads/node, each computes 4 features.
// ---------------------------------------------------------------------------
__global__ void k_l1(const float* __restrict__ W1, const float* __restrict__ b1) {
    __shared__ float w[6 * F1];
    for (int j = threadIdx.x; j < 6 * F1; j += blockDim.x) w[j] = W1[j];
    __syncthreads();
    int i = blockIdx.x * blockDim.x + threadIdx.x;
    if (i >= NN * 16) return;
    int n = i >> 4;
    int c = (i & 15) * 4;
    float dv = d_dinv[n];
    float t[6];
#pragma unroll
    for (int k = 0; k < 6; k++) t[k] = d_acc0[n * P0 + k] + d_p0[n * P0 + k];
    float4 o;
    float* po = (float*)&o;
#pragma unroll
    for (int j = 0; j < 4; j++) {
        float a = 0.f;
#pragma unroll
        for (int k = 0; k < 6; k++) a += t[k] * w[k * F1 + c + j];
        po[j] = dv * relu(dv * a + b1[c + j]);
    }
    *reinterpret_cast<float4*>(&d_p1[n * F1 + c]) = o;
}

// ---------------------------------------------------------------------------
// 5) Edge scatter (pre-W2): acc1[dst] += p1[src]   (16 float4 reds / edge)
// ---------------------------------------------------------------------------
__global__ void k_sc1(const int* __restrict__ ei) {
    int i = blockIdx.x * blockDim.x + threadIdx.x;
    if (i >= NE * 16) return;
    int e = i >> 4;
    int c = (i & 15) * 4;
    int s = ei[e];
    int d = ei[NE + e];
    float4 v = *reinterpret_cast<const float4*>(&d_p1[s * F1 + c]);
    atomicAdd(reinterpret_cast<float4*>(&d_acc1[d * F1 + c]), v);
}

// ---------------------------------------------------------------------------
// 6) t2 = acc1 + p1; out2 = relu(dinv*(t2@W2) + b2);
//    pool[batch[n]] += out2; cnt[batch[n]] += 1.   Fused (no g2/acc2 arrays).
//    128 threads/block (one out feature each), 16 nodes per block.
// ---------------------------------------------------------------------------
__global__ void k_l2pool(const float* __restrict__ W2, const float* __restrict__ b2,
                         const int* __restrict__ batch) {
    __shared__ float w[F1 * F2];
    __shared__ float in_s[F1];
    int tid = threadIdx.x;
    for (int j = tid; j < F1 * F2; j += 128) w[j] = W2[j];
    int base = blockIdx.x * 16;
    for (int t = 0; t < 16; t++) {
        int n = base + t;
        float dv = d_dinv[n];
        __syncthreads();
        if (tid < F1) in_s[tid] = d_acc1[n * F1 + tid] + d_p1[n * F1 + tid];
        __syncthreads();
        float a = 0.f;
#pragma unroll
        for (int k = 0; k < F1; k++) a += in_s[k] * w[k * F2 + tid];
        float v = relu(dv * a + b2[tid]);
        int gid = batch[n];
        atomicAdd(&d_pool[gid * F2 + tid], v);
        if (tid == 0) atomicAdd(&d_cnt[gid], 1.f);
    }
}

// ---------------------------------------------------------------------------
// 7) out[g] = (pool[g]/max(cnt,1)) @ Wfc + bfc      [1000, 2]
// ---------------------------------------------------------------------------
__global__ void k_fc(const float* __restrict__ Wfc, const float* __restrict__ bfc,
                     float* __restrict__ out) {
    int i = blockIdx.x * blockDim.x + threadIdx.x;
    if (i >= NG * 2) return;
    int g = i >> 1;
    int o = i & 1;
    float cnt = d_cnt[g];
    float inv = 1.f / (cnt > 1.f ? cnt : 1.f);
    float a = 0.f;
#pragma unroll 8
    for (int k = 0; k < F2; k++) a += d_pool[g * F2 + k] * Wfc[k * 2 + o];
    out[i] = a * inv + bfc[o];
}

// ---------------------------------------------------------------------------
extern "C" void kernel_launch(void* const* d_in, const int* in_sizes, int n_in,
                              void* d_out, int out_size) {
    const float* x   = (const float*)d_in[0];
    const int*   ei  = (const int*)d_in[1];   // int32 (JAX x64 disabled)
    const int*   bat = (const int*)d_in[2];   // int32
    const float* W1  = (const float*)d_in[3];
    const float* b1  = (const float*)d_in[4];
    const float* W2  = (const float*)d_in[5];
    const float* b2  = (const float*)d_in[6];
    const float* Wfc = (const float*)d_in[7];
    const float* bfc = (const float*)d_in[8];
    float*       out = (float*)d_out;

    k_init<<<(NN * F1 + 255) / 256, 256>>>();
    k_deg<<<(NE + 255) / 256, 256>>>(ei);
    k_dinv<<<(NN + 255) / 256, 256>>>();
    k_p0<<<(NN + 255) / 256, 256>>>(x);
    k_sc0<<<(NE * 2 + 255) / 256, 256>>>(ei);
    k_l1<<<(NN * 16 + 255) / 256, 256>>>(W1, b1);
    k_sc1<<<(NE * 16 + 255) / 256, 256>>>(ei);
    k_l2pool<<<NN / 16, 128>>>(W2, b2, bat);
    k_fc<<<(NG * 2 + 255) / 256, 256>>>(Wfc, bfc, out);
}